// round 17
// baseline (speedup 1.0000x reference)
#include <cuda_runtime.h>

#define DIN  64
#define DOUT 64
#define HH   32
#define HP   16          // h-pairs
#define BB   2048
#define IQ   16          // Din split factor
#define IPQ  (DIN / IQ)  // 4 i's per CTA

// ---- device scratch ----
// w1p record per (o,i,hp): 64B = {0.5*w_f(h0),0.5*w_f(h1) f=0..6, 0.5*B1(h0),0.5*B1(h1)}
__device__ __align__(16) unsigned long long g_w1p[DOUT * DIN * HP * 8];   // 4 MB
// w2: per (o,i,hp): u64 = (W2(h0), W2(h1))
__device__ __align__(16) unsigned long long g_w2[DOUT * DIN * HP];        // 1 MB
__device__ float g_xT[DIN * BB];
__device__ float g_sumB2[DOUT];

// ---- f32x2 helpers ----
__device__ __forceinline__ unsigned long long pack2(float a, float b) {
    unsigned long long v;
    asm("mov.b64 %0, {%1, %2};" : "=l"(v) : "f"(a), "f"(b));
    return v;
}
__device__ __forceinline__ void unpack2(unsigned long long v, float& a, float& b) {
    asm("mov.b64 {%0, %1}, %2;" : "=f"(a), "=f"(b) : "l"(v));
}
__device__ __forceinline__ unsigned long long fma2(unsigned long long a,
                                                   unsigned long long b,
                                                   unsigned long long c) {
    unsigned long long d;
    asm("fma.rn.f32x2 %0, %1, %2, %3;" : "=l"(d) : "l"(a), "l"(b), "l"(c));
    return d;
}
// duplicate lo/hi half of a u64 into both halves (register MOVs, ALU pipe)
__device__ __forceinline__ unsigned long long dup_lo(unsigned long long v) {
    unsigned long long d;
    asm("{\n\t.reg .b32 l, h;\n\tmov.b64 {l, h}, %1;\n\tmov.b64 %0, {l, l};\n\t}"
        : "=l"(d) : "l"(v));
    return d;
}
__device__ __forceinline__ unsigned long long dup_hi(unsigned long long v) {
    unsigned long long d;
    asm("{\n\t.reg .b32 l, h;\n\tmov.b64 {l, h}, %1;\n\tmov.b64 %0, {h, h};\n\t}"
        : "=l"(d) : "l"(v));
    return d;
}
__device__ __forceinline__ float tanh_fast(float x) {
    float y;
    asm("tanh.approx.f32 %0, %1;" : "=f"(y) : "f"(x));
    return y;
}

// features for a b-PAIR, packed (even,odd) per feature: 7 u64 per 2 b's.
// order matches reference: [x, sin1, sin2, sin4, cos1, cos2, cos4]; 2x/4x via double-angle.
__device__ __forceinline__ void make_feats_pair(float xe, float xo, unsigned long long* F) {
    float se1 = __sinf(xe), ce1 = __cosf(xe);
    float te  = se1 + se1;
    float se2 = te * ce1;
    float ce2 = fmaf(-te, se1, 1.f);
    float t2e = se2 + se2;
    float se4 = t2e * ce2;
    float ce4 = fmaf(-t2e, se2, 1.f);
    float so1 = __sinf(xo), co1 = __cosf(xo);
    float to  = so1 + so1;
    float so2 = to * co1;
    float co2 = fmaf(-to, so1, 1.f);
    float t2o = so2 + so2;
    float so4 = t2o * co2;
    float co4 = fmaf(-t2o, so2, 1.f);
    F[0] = pack2(xe,  xo);
    F[1] = pack2(se1, so1);
    F[2] = pack2(se2, so2);
    F[3] = pack2(se4, so4);
    F[4] = pack2(ce1, co1);
    F[5] = pack2(ce2, co2);
    F[6] = pack2(ce4, co4);
}

// one edge-MLP evaluation for a b-pair at one scalar h. d0..d6,bd,wd are
// weight/bias/W2 values duplicated in both halves; F packs (even,odd) feats.
__device__ __forceinline__ void eval_pair(
    unsigned long long d0, unsigned long long d1, unsigned long long d2,
    unsigned long long d3, unsigned long long d4, unsigned long long d5,
    unsigned long long d6, unsigned long long bd, unsigned long long wd,
    const unsigned long long* F, unsigned long long& acc) {
    unsigned long long u = fma2(d0, F[0], bd);      // bd = dup(0.5*B1_h)
    u = fma2(d1, F[1], u);
    u = fma2(d2, F[2], u);
    u = fma2(d3, F[3], u);
    u = fma2(d4, F[4], u);
    u = fma2(d5, F[5], u);
    u = fma2(d6, F[6], u);                          // u = (hE/2, hO/2)
    float a0, a1;
    unpack2(u, a0, a1);
    unsigned long long tp = pack2(tanh_fast(a0), tanh_fast(a1));
    unsigned long long s = fma2(u, tp, u);          // silu(h) = (h/2)(1+tanh(h/2))
    acc = fma2(s, wd, acc);                         // acc = (phiE, phiO) partial
}

// ---- prologue 1: tiled x transpose (coalesced both sides) ----
__global__ void prep_x_t(const float* __restrict__ x) {
    __shared__ float tile[32][33];
    int bx = blockIdx.x;
    int by = blockIdx.y;
    int tx = threadIdx.x, ty = threadIdx.y;   // 32 x 8
#pragma unroll
    for (int k = 0; k < 4; k++) {
        int b = bx * 32 + ty + k * 8;
        tile[ty + k * 8][tx] = x[b * DIN + by * 32 + tx];
    }
    __syncthreads();
#pragma unroll
    for (int k = 0; k < 4; k++) {
        int i = by * 32 + ty + k * 8;
        g_xT[i * BB + bx * 32 + tx] = tile[tx][ty + k * 8];
    }
}

// ---- prologue 2: weight repack + B2 row-sum ----
#define NRP (DOUT * DIN * HP)
__global__ void prep_w(const float* __restrict__ W1, const float* __restrict__ W2,
                       const float* __restrict__ B1, const float* __restrict__ B2) {
    int t = blockIdx.x * 256 + threadIdx.x;
    if (t < NRP) {
        int hp = t & 15;
        int i  = (t >> 4) & 63;
        int o  = t >> 10;
        int h0 = hp * 2, h1 = h0 + 1;

        const float* w1b = W1 + (((size_t)i * DOUT + o) * HH) * 7;  // W1[i][o][h][f]
        float* dst = ((float*)g_w1p) + (size_t)t * 16;
#pragma unroll
        for (int f = 0; f < 7; f++) {
            dst[2 * f]     = 0.5f * w1b[h0 * 7 + f];
            dst[2 * f + 1] = 0.5f * w1b[h1 * 7 + f];
        }
        const float* b1b = B1 + ((size_t)i * DOUT + o) * HH;
        dst[14] = 0.5f * b1b[h0];
        dst[15] = 0.5f * b1b[h1];

        const float* w2b = W2 + ((size_t)i * DOUT + o) * HH;  // W2[i][o][0][h]
        float* d2 = ((float*)g_w2) + (((size_t)o * DIN + i) * HP + hp) * 2;
        d2[0] = w2b[h0];
        d2[1] = w2b[h1];
        return;
    }
    t -= NRP;
    if (t < DOUT) {
        float s = 0.f;
        for (int i = 0; i < DIN; i++) s += B2[i * DOUT + t];
        g_sumB2[t] = s;
    }
}

// ---- prologue 3: initialize out with bias row-sums (atomic accumulation base) ----
__global__ void out_init(float* __restrict__ out) {
    int t = blockIdx.x * 256 + threadIdx.x;      // t = b*DOUT + o
    if (t < BB * DOUT) out[t] = g_sumB2[t & 63];
}

// ---- main fused kernel (launch #4 -> profiled) ----
// CTA = 4 warps (128 thr), one (o, iq, bo): 4 i's, 1024 b's. 4.5KB slice in smem.
// Lane owns 8 b's as 4 (even,odd) PAIRS packed per-feature (b-pair f32x2 packing):
// each 4.5-LDS weight block now feeds 72 FFMA2 (2x R16) -> LDS/SM halves, and
// transient in-register weight dups (dup_lo/dup_hi) replace pre-duplicated feats.
// 8 independent eval chains per warp. grid = 64 o * 16 iq * 2 bo = 2048 CTAs.
__global__ void __launch_bounds__(128, 4) kan_main(float* __restrict__ out) {
    __shared__ __align__(16) ulonglong2 s_w1[IPQ * HP * 4];          // 4 KB
    __shared__ __align__(16) unsigned long long s_w2[IPQ * HP];      // 512 B

    int lane = threadIdx.x & 31;
    int w    = threadIdx.x >> 5;
    int o    = blockIdx.x & 63;
    int iq   = (blockIdx.x >> 6) & 15;
    int bo   = blockIdx.x >> 10;            // 0..1
    int b0   = bo * 1024 + w * 256 + lane;  // pairs: (b0+p*64, b0+p*64+32), p=0..3
    int i0   = iq * IPQ;

    // cooperative weight-slice load (coalesced LDG.128 -> STS.128)
    {
        const ulonglong2* gw1 = ((const ulonglong2*)g_w1p) + ((size_t)o * DIN + i0) * (HP * 4);
        const ulonglong2* gw2 = ((const ulonglong2*)g_w2)  + ((size_t)o * DIN + i0) * (HP / 2);
#pragma unroll
        for (int t = threadIdx.x; t < IPQ * HP * 4; t += 128) s_w1[t] = gw1[t];
        if (threadIdx.x < IPQ * HP / 2)
            ((ulonglong2*)s_w2)[threadIdx.x] = gw2[threadIdx.x];
    }
    __syncthreads();

    unsigned long long acc0 = 0ull, acc1 = 0ull, acc2 = 0ull, acc3 = 0ull;
    unsigned long long F0[7], F1[7], F2[7], F3[7];

    const float* xr = g_xT + i0 * BB + b0;

#pragma unroll 1
    for (int ii = 0; ii < IPQ; ii++) {
        const float* xn = xr + ii * BB;
        make_feats_pair(xn[0],   xn[32],  F0);
        make_feats_pair(xn[64],  xn[96],  F1);
        make_feats_pair(xn[128], xn[160], F2);
        make_feats_pair(xn[192], xn[224], F3);

        const ulonglong2* wr        = s_w1 + ii * (HP * 4);
        const unsigned long long* w2r = s_w2 + ii * HP;

#pragma unroll 1
        for (int hp = 0; hp < HP; hp++) {
            ulonglong2 q0 = wr[hp * 4 + 0];   // (w0h0,w0h1),(w1h0,w1h1)
            ulonglong2 q1 = wr[hp * 4 + 1];   // (w2.,.),(w3.,.)
            ulonglong2 q2 = wr[hp * 4 + 2];   // (w4.,.),(w5.,.)
            ulonglong2 q3 = wr[hp * 4 + 3];   // (w6h0,w6h1),(B1h0,B1h1)
            unsigned long long w2p = w2r[hp]; // (W2h0, W2h1)

            // ---- h = h0 (lo halves duplicated) ----
            {
                unsigned long long d0 = dup_lo(q0.x), d1 = dup_lo(q0.y);
                unsigned long long d2 = dup_lo(q1.x), d3 = dup_lo(q1.y);
                unsigned long long d4 = dup_lo(q2.x), d5 = dup_lo(q2.y);
                unsigned long long d6 = dup_lo(q3.x), bd = dup_lo(q3.y);
                unsigned long long wd = dup_lo(w2p);
                eval_pair(d0,d1,d2,d3,d4,d5,d6,bd,wd, F0, acc0);
                eval_pair(d0,d1,d2,d3,d4,d5,d6,bd,wd, F1, acc1);
                eval_pair(d0,d1,d2,d3,d4,d5,d6,bd,wd, F2, acc2);
                eval_pair(d0,d1,d2,d3,d4,d5,d6,bd,wd, F3, acc3);
            }
            // ---- h = h1 (hi halves duplicated) ----
            {
                unsigned long long d0 = dup_hi(q0.x), d1 = dup_hi(q0.y);
                unsigned long long d2 = dup_hi(q1.x), d3 = dup_hi(q1.y);
                unsigned long long d4 = dup_hi(q2.x), d5 = dup_hi(q2.y);
                unsigned long long d6 = dup_hi(q3.x), bd = dup_hi(q3.y);
                unsigned long long wd = dup_hi(w2p);
                eval_pair(d0,d1,d2,d3,d4,d5,d6,bd,wd, F0, acc0);
                eval_pair(d0,d1,d2,d3,d4,d5,d6,bd,wd, F1, acc1);
                eval_pair(d0,d1,d2,d3,d4,d5,d6,bd,wd, F2, acc2);
                eval_pair(d0,d1,d2,d3,d4,d5,d6,bd,wd, F3, acc3);
            }
        }
    }

    float re, ro;
    unpack2(acc0, re, ro);
    atomicAdd(&out[(size_t)(b0      ) * DOUT + o], re);
    atomicAdd(&out[(size_t)(b0 + 32 ) * DOUT + o], ro);
    unpack2(acc1, re, ro);
    atomicAdd(&out[(size_t)(b0 + 64 ) * DOUT + o], re);
    atomicAdd(&out[(size_t)(b0 + 96 ) * DOUT + o], ro);
    unpack2(acc2, re, ro);
    atomicAdd(&out[(size_t)(b0 + 128) * DOUT + o], re);
    atomicAdd(&out[(size_t)(b0 + 160) * DOUT + o], ro);
    unpack2(acc3, re, ro);
    atomicAdd(&out[(size_t)(b0 + 192) * DOUT + o], re);
    atomicAdd(&out[(size_t)(b0 + 224) * DOUT + o], ro);
}

extern "C" void kernel_launch(void* const* d_in, const int* in_sizes, int n_in,
                              void* d_out, int out_size) {
    const float* x  = (const float*)d_in[0];
    const float* W1 = (const float*)d_in[1];
    const float* W2 = (const float*)d_in[2];
    const float* B1 = (const float*)d_in[3];
    const float* B2 = (const float*)d_in[4];
    (void)in_sizes; (void)n_in; (void)out_size;

    dim3 tb(32, 8);
    dim3 tg(64, 2);
    prep_x_t<<<tg, tb>>>(x);                                    // launch 1
    prep_w<<<(NRP + DOUT + 255) / 256, 256>>>(W1, W2, B1, B2);  // launch 2
    out_init<<<(BB * DOUT + 255) / 256, 256>>>((float*)d_out);  // launch 3
    kan_main<<<2048, 128>>>((float*)d_out);                     // launch 4 (profiled)
}